// round 5
// baseline (speedup 1.0000x reference)
#include <cuda_runtime.h>
#include <math.h>

// Problem constants
#define B_ 8
#define N_ 4096
#define S_ 512
#define D_ 512
#define H_ 8
#define HD_ 64

// Scratch (allocation-free rule: __device__ globals)
__device__ float g_Q[(size_t)B_ * N_ * D_];
__device__ float g_KV[(size_t)B_ * S_ * 2 * D_];
__device__ float g_O[(size_t)B_ * N_ * D_];

// ---------------------------------------------------------------------------
// tf32 helpers
// ---------------------------------------------------------------------------
__device__ __forceinline__ unsigned f2tf(float x) {
    unsigned r;
    asm("cvt.rna.tf32.f32 %0, %1;" : "=r"(r) : "f"(x));
    return r;
}

__device__ __forceinline__ void mma_tf32(float* d, const unsigned* a, const unsigned* b) {
    asm volatile(
        "mma.sync.aligned.m16n8k8.row.col.f32.tf32.tf32.f32 "
        "{%0,%1,%2,%3}, {%4,%5,%6,%7}, {%8,%9}, {%0,%1,%2,%3};\n"
        : "+f"(d[0]), "+f"(d[1]), "+f"(d[2]), "+f"(d[3])
        : "r"(a[0]), "r"(a[1]), "r"(a[2]), "r"(a[3]), "r"(b[0]), "r"(b[1]));
}

// ---------------------------------------------------------------------------
// GEMM: C[m][n] = sum_k A[m][k] * W[n][k] + bias[n]   (tf32 tensor cores)
// BM=BN=128, BK=32. 256 threads = 8 warps (2m x 4n), warp tile 64x32.
// ---------------------------------------------------------------------------
#define GPAD 36
#define GTILE (128 * GPAD)

__global__ __launch_bounds__(256) void gemm_tf32(
    const float* __restrict__ A, const float* __restrict__ W,
    const float* __restrict__ bias, float* __restrict__ C,
    int M, int Nd, int Kd)
{
    extern __shared__ unsigned sg[];
    unsigned* As = sg;                // [2][128][36]
    unsigned* Ws = sg + 2 * GTILE;    // [2][128][36]

    const int tid = threadIdx.x;
    const int lane = tid & 31;
    const int warp = tid >> 5;
    const int wm = warp >> 2;         // 0..1
    const int wn = warp & 3;          // 0..3
    const int m0 = blockIdx.y * 128;
    const int n0 = blockIdx.x * 128;

    float acc[4][4][4];
#pragma unroll
    for (int i = 0; i < 4; i++)
#pragma unroll
        for (int j = 0; j < 4; j++)
#pragma unroll
            for (int r = 0; r < 4; r++) acc[i][j][r] = 0.f;

    float4 pa[4], pw[4];
    const int nkt = Kd / 32;

    // prefetch tile 0
#pragma unroll
    for (int l = 0; l < 4; l++) {
        int idx = tid + l * 256;
        int row = idx >> 3;
        int c4 = (idx & 7) * 4;
        pa[l] = *(const float4*)(A + (size_t)(m0 + row) * Kd + c4);
        pw[l] = *(const float4*)(W + (size_t)(n0 + row) * Kd + c4);
    }
#pragma unroll
    for (int l = 0; l < 4; l++) {
        int idx = tid + l * 256;
        int row = idx >> 3;
        int c4 = (idx & 7) * 4;
        uint4 ua = make_uint4(f2tf(pa[l].x), f2tf(pa[l].y), f2tf(pa[l].z), f2tf(pa[l].w));
        uint4 uw = make_uint4(f2tf(pw[l].x), f2tf(pw[l].y), f2tf(pw[l].z), f2tf(pw[l].w));
        *(uint4*)(As + row * GPAD + c4) = ua;
        *(uint4*)(Ws + row * GPAD + c4) = uw;
    }
    __syncthreads();

    for (int kt = 0; kt < nkt; kt++) {
        if (kt + 1 < nkt) {
#pragma unroll
            for (int l = 0; l < 4; l++) {
                int idx = tid + l * 256;
                int row = idx >> 3;
                int c4 = (idx & 7) * 4;
                pa[l] = *(const float4*)(A + (size_t)(m0 + row) * Kd + (kt + 1) * 32 + c4);
                pw[l] = *(const float4*)(W + (size_t)(n0 + row) * Kd + (kt + 1) * 32 + c4);
            }
        }
        const unsigned* Ab = As + (kt & 1) * GTILE + (wm * 64) * GPAD;
        const unsigned* Wb = Ws + (kt & 1) * GTILE + (wn * 32) * GPAD;

#pragma unroll
        for (int ks = 0; ks < 32; ks += 8) {
            unsigned af[4][4], bf[4][2];
#pragma unroll
            for (int mt = 0; mt < 4; mt++) {
                const unsigned* p = Ab + (mt * 16 + (lane >> 2)) * GPAD + ks + (lane & 3);
                af[mt][0] = p[0];
                af[mt][1] = p[8 * GPAD];
                af[mt][2] = p[4];
                af[mt][3] = p[8 * GPAD + 4];
            }
#pragma unroll
            for (int nt = 0; nt < 4; nt++) {
                const unsigned* p = Wb + (nt * 8 + (lane >> 2)) * GPAD + ks + (lane & 3);
                bf[nt][0] = p[0];
                bf[nt][1] = p[4];
            }
#pragma unroll
            for (int mt = 0; mt < 4; mt++)
#pragma unroll
                for (int nt = 0; nt < 4; nt++)
                    mma_tf32(acc[mt][nt], af[mt], bf[nt]);
        }
        __syncthreads();
        if (kt + 1 < nkt) {
            unsigned* Ad = As + ((kt + 1) & 1) * GTILE;
            unsigned* Wd = Ws + ((kt + 1) & 1) * GTILE;
#pragma unroll
            for (int l = 0; l < 4; l++) {
                int idx = tid + l * 256;
                int row = idx >> 3;
                int c4 = (idx & 7) * 4;
                uint4 ua = make_uint4(f2tf(pa[l].x), f2tf(pa[l].y), f2tf(pa[l].z), f2tf(pa[l].w));
                uint4 uw = make_uint4(f2tf(pw[l].x), f2tf(pw[l].y), f2tf(pw[l].z), f2tf(pw[l].w));
                *(uint4*)(Ad + row * GPAD + c4) = ua;
                *(uint4*)(Wd + row * GPAD + c4) = uw;
            }
            __syncthreads();
        }
    }

    // epilogue + bias
#pragma unroll
    for (int mt = 0; mt < 4; mt++) {
        int row0 = m0 + wm * 64 + mt * 16 + (lane >> 2);
#pragma unroll
        for (int nt = 0; nt < 4; nt++) {
            int col = n0 + wn * 32 + nt * 8 + (lane & 3) * 2;
            float2 bb = *(const float2*)(bias + col);
            float2 v0, v1;
            v0.x = acc[mt][nt][0] + bb.x;
            v0.y = acc[mt][nt][1] + bb.y;
            v1.x = acc[mt][nt][2] + bb.x;
            v1.y = acc[mt][nt][3] + bb.y;
            *(float2*)(C + (size_t)row0 * Nd + col) = v0;
            *(float2*)(C + (size_t)(row0 + 8) * Nd + col) = v1;
        }
    }
}

// ---------------------------------------------------------------------------
// Flash attention, tf32 tensor cores. CTA = 64 queries of one (b,h).
// 128 threads (4 warps), warp owns 16 q-rows. S-tiles of 64.
// ---------------------------------------------------------------------------
#define APAD 68
// u32 offsets in dynamic smem
#define OFF_QS 0
#define OFF_KS (64 * APAD)
#define OFF_PS (2 * 64 * APAD)
#define OFF_VS (3 * 64 * APAD)
#define OFF_MA (3 * 64 * APAD + 64 * 64)
#define ATTN_SMEM_U32 (3 * 64 * APAD + 64 * 64 + 512)

// V swizzle: element (d, s) stored at d*64 + ((s + 4d + (d>>3)) & 63)
__device__ __forceinline__ int vswz(int d, int s) {
    return d * 64 + ((s + 4 * d + (d >> 3)) & 63);
}

__global__ __launch_bounds__(128) void attn_tf32(
    const float* __restrict__ Q, const float* __restrict__ KV,
    const int* __restrict__ mask, float* __restrict__ O)
{
    extern __shared__ unsigned sa[];
    unsigned* Qs = sa + OFF_QS;   // [64][68] tf32, [q][d]
    unsigned* Ks = sa + OFF_KS;   // [64][68] tf32, [s][d]
    unsigned* Ps = sa + OFF_PS;   // [64][68] tf32, [q][s]
    unsigned* Vs = sa + OFF_VS;   // [64*64] tf32, swizzled [d][s]
    float* mAdd = (float*)(sa + OFF_MA);  // [512]

    const int tid = threadIdx.x;
    const int lane = tid & 31;
    const int warp = tid >> 5;
    const int n0 = blockIdx.x * 64;
    const int h = blockIdx.y;
    const int b = blockIdx.z;

    const float* Qb = Q + ((size_t)b * N_ + n0) * D_ + h * HD_;
    const float* Kb = KV + (size_t)b * S_ * (2 * D_) + h * HD_;
    const float* Vb = Kb + D_;
    const int* mb = mask + b * S_;
    float* Ob = O + ((size_t)b * N_ + n0) * D_ + h * HD_;

    // load Q tile (pre-scaled by 0.125), cvt to tf32
#pragma unroll
    for (int l = 0; l < 8; l++) {
        int idx = tid + l * 128;
        int q = idx >> 4;
        int d4 = (idx & 15) * 4;
        float4 v = *(const float4*)(Qb + (size_t)q * D_ + d4);
        uint4 u = make_uint4(f2tf(v.x * 0.125f), f2tf(v.y * 0.125f),
                             f2tf(v.z * 0.125f), f2tf(v.w * 0.125f));
        *(uint4*)(Qs + q * APAD + d4) = u;
    }
    // mask addends
    for (int s = tid; s < S_; s += 128) mAdd[s] = mb[s] ? -1e5f : 0.f;

    float o[8][4];
#pragma unroll
    for (int i = 0; i < 8; i++)
#pragma unroll
        for (int r = 0; r < 4; r++) o[i][r] = 0.f;
    float mrow0 = -1e30f, mrow1 = -1e30f, lrow0 = 0.f, lrow1 = 0.f;

    const int q0 = warp * 16 + (lane >> 2);

    __syncthreads();

    for (int st = 0; st < S_; st += 64) {
        // load K tile [s][d] and V tile transposed+swizzled [d][s]
#pragma unroll
        for (int l = 0; l < 8; l++) {
            int idx = tid + l * 128;
            int s = idx >> 4;
            int d4 = (idx & 15) * 4;
            float4 vk = *(const float4*)(Kb + (size_t)(st + s) * (2 * D_) + d4);
            uint4 uk = make_uint4(f2tf(vk.x), f2tf(vk.y), f2tf(vk.z), f2tf(vk.w));
            *(uint4*)(Ks + s * APAD + d4) = uk;
            float4 vv = *(const float4*)(Vb + (size_t)(st + s) * (2 * D_) + d4);
            Vs[vswz(d4 + 0, s)] = f2tf(vv.x);
            Vs[vswz(d4 + 1, s)] = f2tf(vv.y);
            Vs[vswz(d4 + 2, s)] = f2tf(vv.z);
            Vs[vswz(d4 + 3, s)] = f2tf(vv.w);
        }
        __syncthreads();

        // QK^T: scores [16q x 64s] per warp
        float sc[8][4];
#pragma unroll
        for (int nt = 0; nt < 8; nt++)
#pragma unroll
            for (int r = 0; r < 4; r++) sc[nt][r] = 0.f;

#pragma unroll
        for (int ks = 0; ks < 64; ks += 8) {
            unsigned af[4];
            const unsigned* pq = Qs + q0 * APAD + ks + (lane & 3);
            af[0] = pq[0];
            af[1] = pq[8 * APAD];
            af[2] = pq[4];
            af[3] = pq[8 * APAD + 4];
#pragma unroll
            for (int nt = 0; nt < 8; nt++) {
                unsigned bf[2];
                const unsigned* pk = Ks + (nt * 8 + (lane >> 2)) * APAD + ks + (lane & 3);
                bf[0] = pk[0];
                bf[1] = pk[4];
                mma_tf32(sc[nt], af, bf);
            }
        }

        // mask + online softmax (rows q0, q0+8)
        float rm0 = -1e30f, rm1 = -1e30f;
#pragma unroll
        for (int nt = 0; nt < 8; nt++) {
            int col = st + nt * 8 + (lane & 3) * 2;
            float a0 = mAdd[col], a1 = mAdd[col + 1];
            sc[nt][0] += a0; sc[nt][1] += a1;
            sc[nt][2] += a0; sc[nt][3] += a1;
            rm0 = fmaxf(rm0, fmaxf(sc[nt][0], sc[nt][1]));
            rm1 = fmaxf(rm1, fmaxf(sc[nt][2], sc[nt][3]));
        }
        rm0 = fmaxf(rm0, __shfl_xor_sync(0xffffffffu, rm0, 1));
        rm0 = fmaxf(rm0, __shfl_xor_sync(0xffffffffu, rm0, 2));
        rm1 = fmaxf(rm1, __shfl_xor_sync(0xffffffffu, rm1, 1));
        rm1 = fmaxf(rm1, __shfl_xor_sync(0xffffffffu, rm1, 2));

        float mn0 = fmaxf(mrow0, rm0), mn1 = fmaxf(mrow1, rm1);
        float c0 = __expf(mrow0 - mn0), c1 = __expf(mrow1 - mn1);
        float rs0 = 0.f, rs1 = 0.f;
#pragma unroll
        for (int nt = 0; nt < 8; nt++) {
            sc[nt][0] = __expf(sc[nt][0] - mn0);
            sc[nt][1] = __expf(sc[nt][1] - mn0);
            sc[nt][2] = __expf(sc[nt][2] - mn1);
            sc[nt][3] = __expf(sc[nt][3] - mn1);
            rs0 += sc[nt][0] + sc[nt][1];
            rs1 += sc[nt][2] + sc[nt][3];
        }
        rs0 += __shfl_xor_sync(0xffffffffu, rs0, 1);
        rs0 += __shfl_xor_sync(0xffffffffu, rs0, 2);
        rs1 += __shfl_xor_sync(0xffffffffu, rs1, 1);
        rs1 += __shfl_xor_sync(0xffffffffu, rs1, 2);

        lrow0 = lrow0 * c0 + rs0;
        lrow1 = lrow1 * c1 + rs1;
        mrow0 = mn0;
        mrow1 = mn1;

        // rescale O accumulators
#pragma unroll
        for (int dt = 0; dt < 8; dt++) {
            o[dt][0] *= c0; o[dt][1] *= c0;
            o[dt][2] *= c1; o[dt][3] *= c1;
        }

        // write P to smem (tf32)
#pragma unroll
        for (int nt = 0; nt < 8; nt++) {
            int col = nt * 8 + (lane & 3) * 2;
            *(uint2*)(Ps + q0 * APAD + col) = make_uint2(f2tf(sc[nt][0]), f2tf(sc[nt][1]));
            *(uint2*)(Ps + (q0 + 8) * APAD + col) = make_uint2(f2tf(sc[nt][2]), f2tf(sc[nt][3]));
        }
        __syncwarp();

        // O += P @ V
#pragma unroll
        for (int ss = 0; ss < 64; ss += 8) {
            unsigned af[4];
            const unsigned* pp = Ps + q0 * APAD + ss + (lane & 3);
            af[0] = pp[0];
            af[1] = pp[8 * APAD];
            af[2] = pp[4];
            af[3] = pp[8 * APAD + 4];
#pragma unroll
            for (int dt = 0; dt < 8; dt++) {
                int d = dt * 8 + (lane >> 2);
                unsigned bf[2];
                bf[0] = Vs[vswz(d, ss + (lane & 3))];
                bf[1] = Vs[vswz(d, ss + 4 + (lane & 3))];
                mma_tf32(o[dt], af, bf);
            }
        }
        __syncthreads();
    }

    // epilogue: normalize and store
    float inv0 = 1.0f / lrow0, inv1 = 1.0f / lrow1;
#pragma unroll
    for (int dt = 0; dt < 8; dt++) {
        int col = dt * 8 + (lane & 3) * 2;
        float2 v0, v1;
        v0.x = o[dt][0] * inv0; v0.y = o[dt][1] * inv0;
        v1.x = o[dt][2] * inv1; v1.y = o[dt][3] * inv1;
        *(float2*)(Ob + (size_t)q0 * D_ + col) = v0;
        *(float2*)(Ob + (size_t)(q0 + 8) * D_ + col) = v1;
    }
}

// ---------------------------------------------------------------------------
// Launch. Inputs: x, context, context_mask(int32), wq, bq, wkv, bkv, wp, bp
// ---------------------------------------------------------------------------
extern "C" void kernel_launch(void* const* d_in, const int* in_sizes, int n_in,
                              void* d_out, int out_size)
{
    const float* x = (const float*)d_in[0];
    const float* ctx = (const float*)d_in[1];
    const int* mask = (const int*)d_in[2];
    const float* wq = (const float*)d_in[3];
    const float* bq = (const float*)d_in[4];
    const float* wkv = (const float*)d_in[5];
    const float* bkv = (const float*)d_in[6];
    const float* wp = (const float*)d_in[7];
    const float* bp = (const float*)d_in[8];
    float* out = (float*)d_out;

    float *Qp, *KVp, *Op;
    cudaGetSymbolAddress((void**)&Qp, g_Q);
    cudaGetSymbolAddress((void**)&KVp, g_KV);
    cudaGetSymbolAddress((void**)&Op, g_O);

    int gemm_smem = 4 * GTILE * (int)sizeof(unsigned);   // 73728
    int attn_smem = ATTN_SMEM_U32 * (int)sizeof(unsigned);

    cudaFuncSetAttribute((const void*)gemm_tf32,
                         cudaFuncAttributeMaxDynamicSharedMemorySize, gemm_smem);
    cudaFuncSetAttribute((const void*)attn_tf32,
                         cudaFuncAttributeMaxDynamicSharedMemorySize, attn_smem);

    // Q projection: [B*N, D] x [D, D]^T
    gemm_tf32<<<dim3(D_ / 128, (B_ * N_) / 128), 256, gemm_smem>>>(x, wq, bq, Qp, B_ * N_, D_, D_);
    // KV projection: [B*S, D] x [2D, D]^T
    gemm_tf32<<<dim3((2 * D_) / 128, (B_ * S_) / 128), 256, gemm_smem>>>(ctx, wkv, bkv, KVp, B_ * S_, 2 * D_, D_);
    // attention
    attn_tf32<<<dim3(N_ / 64, H_, B_), 128, attn_smem>>>(Qp, KVp, mask, Op);
    // output projection
    gemm_tf32<<<dim3(D_ / 128, (B_ * N_) / 128), 256, gemm_smem>>>(Op, wp, bp, out, B_ * N_, D_, D_);
}

// round 8
// speedup vs baseline: 1.1694x; 1.1694x over previous
#include <cuda_runtime.h>
#include <math.h>

// Problem constants
#define B_ 8
#define N_ 4096
#define S_ 512
#define D_ 512
#define H_ 8
#define HD_ 64

// Scratch (allocation-free rule: __device__ globals)
__device__ float g_Q[(size_t)B_ * N_ * D_];
__device__ float g_KV[(size_t)B_ * S_ * 2 * D_];
__device__ float g_O[(size_t)B_ * N_ * D_];

// ---------------------------------------------------------------------------
// tf32 helpers
// ---------------------------------------------------------------------------
__device__ __forceinline__ unsigned f2tf(float x) {
    unsigned r;
    asm("cvt.rna.tf32.f32 %0, %1;" : "=r"(r) : "f"(x));
    return r;
}

__device__ __forceinline__ void mma_tf32(float* d, const unsigned* a, const unsigned* b) {
    asm volatile(
        "mma.sync.aligned.m16n8k8.row.col.f32.tf32.tf32.f32 "
        "{%0,%1,%2,%3}, {%4,%5,%6,%7}, {%8,%9}, {%0,%1,%2,%3};\n"
        : "+f"(d[0]), "+f"(d[1]), "+f"(d[2]), "+f"(d[3])
        : "r"(a[0]), "r"(a[1]), "r"(a[2]), "r"(a[3]), "r"(b[0]), "r"(b[1]));
}

// ---------------------------------------------------------------------------
// GEMM: C[m][n] = sum_k A[m][k] * W[n][k] + bias[n]   (tf32 tensor cores)
// BM=BN=128, BK=32. 256 threads = 8 warps (2m x 4n), warp tile 64x32.
// __launch_bounds__(256,2): cap regs at 128 so 2 CTAs/SM are resident.
// ---------------------------------------------------------------------------
#define GPAD 36
#define GTILE (128 * GPAD)

__global__ __launch_bounds__(256, 2) void gemm_tf32(
    const float* __restrict__ A, const float* __restrict__ W,
    const float* __restrict__ bias, float* __restrict__ C,
    int M, int Nd, int Kd)
{
    extern __shared__ unsigned sg[];
    unsigned* As = sg;                // [2][128][36]
    unsigned* Ws = sg + 2 * GTILE;    // [2][128][36]

    const int tid = threadIdx.x;
    const int lane = tid & 31;
    const int warp = tid >> 5;
    const int wm = warp >> 2;         // 0..1
    const int wn = warp & 3;          // 0..3
    const int m0 = blockIdx.y * 128;
    const int n0 = blockIdx.x * 128;

    float acc[4][4][4];
#pragma unroll
    for (int i = 0; i < 4; i++)
#pragma unroll
        for (int j = 0; j < 4; j++)
#pragma unroll
            for (int r = 0; r < 4; r++) acc[i][j][r] = 0.f;

    float4 pa[4], pw[4];
    const int nkt = Kd / 32;

    // prefetch tile 0
#pragma unroll
    for (int l = 0; l < 4; l++) {
        int idx = tid + l * 256;
        int row = idx >> 3;
        int c4 = (idx & 7) * 4;
        pa[l] = *(const float4*)(A + (size_t)(m0 + row) * Kd + c4);
        pw[l] = *(const float4*)(W + (size_t)(n0 + row) * Kd + c4);
    }
#pragma unroll
    for (int l = 0; l < 4; l++) {
        int idx = tid + l * 256;
        int row = idx >> 3;
        int c4 = (idx & 7) * 4;
        uint4 ua = make_uint4(f2tf(pa[l].x), f2tf(pa[l].y), f2tf(pa[l].z), f2tf(pa[l].w));
        uint4 uw = make_uint4(f2tf(pw[l].x), f2tf(pw[l].y), f2tf(pw[l].z), f2tf(pw[l].w));
        *(uint4*)(As + row * GPAD + c4) = ua;
        *(uint4*)(Ws + row * GPAD + c4) = uw;
    }
    __syncthreads();

    for (int kt = 0; kt < nkt; kt++) {
        if (kt + 1 < nkt) {
#pragma unroll
            for (int l = 0; l < 4; l++) {
                int idx = tid + l * 256;
                int row = idx >> 3;
                int c4 = (idx & 7) * 4;
                pa[l] = *(const float4*)(A + (size_t)(m0 + row) * Kd + (kt + 1) * 32 + c4);
                pw[l] = *(const float4*)(W + (size_t)(n0 + row) * Kd + (kt + 1) * 32 + c4);
            }
        }
        const unsigned* Ab = As + (kt & 1) * GTILE + (wm * 64) * GPAD;
        const unsigned* Wb = Ws + (kt & 1) * GTILE + (wn * 32) * GPAD;

#pragma unroll
        for (int ks = 0; ks < 32; ks += 8) {
            unsigned af[4][4], bf[4][2];
#pragma unroll
            for (int mt = 0; mt < 4; mt++) {
                const unsigned* p = Ab + (mt * 16 + (lane >> 2)) * GPAD + ks + (lane & 3);
                af[mt][0] = p[0];
                af[mt][1] = p[8 * GPAD];
                af[mt][2] = p[4];
                af[mt][3] = p[8 * GPAD + 4];
            }
#pragma unroll
            for (int nt = 0; nt < 4; nt++) {
                const unsigned* p = Wb + (nt * 8 + (lane >> 2)) * GPAD + ks + (lane & 3);
                bf[nt][0] = p[0];
                bf[nt][1] = p[4];
            }
#pragma unroll
            for (int mt = 0; mt < 4; mt++)
#pragma unroll
                for (int nt = 0; nt < 4; nt++)
                    mma_tf32(acc[mt][nt], af[mt], bf[nt]);
        }
        // Store next tile into the OTHER buffer. Its previous readers (iter
        // kt-1) finished before the barrier at the end of iter kt-1, so no
        // barrier is needed between compute and this store.
        if (kt + 1 < nkt) {
            unsigned* Ad = As + ((kt + 1) & 1) * GTILE;
            unsigned* Wd = Ws + ((kt + 1) & 1) * GTILE;
#pragma unroll
            for (int l = 0; l < 4; l++) {
                int idx = tid + l * 256;
                int row = idx >> 3;
                int c4 = (idx & 7) * 4;
                uint4 ua = make_uint4(f2tf(pa[l].x), f2tf(pa[l].y), f2tf(pa[l].z), f2tf(pa[l].w));
                uint4 uw = make_uint4(f2tf(pw[l].x), f2tf(pw[l].y), f2tf(pw[l].z), f2tf(pw[l].w));
                *(uint4*)(Ad + row * GPAD + c4) = ua;
                *(uint4*)(Wd + row * GPAD + c4) = uw;
            }
            __syncthreads();
        }
    }

    // epilogue + bias
#pragma unroll
    for (int mt = 0; mt < 4; mt++) {
        int row0 = m0 + wm * 64 + mt * 16 + (lane >> 2);
#pragma unroll
        for (int nt = 0; nt < 4; nt++) {
            int col = n0 + wn * 32 + nt * 8 + (lane & 3) * 2;
            float2 bb = *(const float2*)(bias + col);
            float2 v0, v1;
            v0.x = acc[mt][nt][0] + bb.x;
            v0.y = acc[mt][nt][1] + bb.y;
            v1.x = acc[mt][nt][2] + bb.x;
            v1.y = acc[mt][nt][3] + bb.y;
            *(float2*)(C + (size_t)row0 * Nd + col) = v0;
            *(float2*)(C + (size_t)(row0 + 8) * Nd + col) = v1;
        }
    }
}

// ---------------------------------------------------------------------------
// Flash attention, tf32 tensor cores. CTA = 128 queries of one (b,h).
// 256 threads (8 warps), each warp owns 16 q-rows. S-tiles of 64.
// ---------------------------------------------------------------------------
#define APAD 68
// u32 offsets in dynamic smem
#define OFF_QS 0
#define OFF_KS (128 * APAD)
#define OFF_PS (128 * APAD + 64 * APAD)
#define OFF_VS (2 * 128 * APAD + 64 * APAD)
#define OFF_MA (2 * 128 * APAD + 64 * APAD + 64 * 64)
#define ATTN_SMEM_U32 (2 * 128 * APAD + 64 * APAD + 64 * 64 + 512)

// V swizzle: element (d, s) stored at d*64 + ((s + 4d + (d>>3)) & 63)
__device__ __forceinline__ int vswz(int d, int s) {
    return d * 64 + ((s + 4 * d + (d >> 3)) & 63);
}

__global__ __launch_bounds__(256, 2) void attn_tf32(
    const float* __restrict__ Q, const float* __restrict__ KV,
    const int* __restrict__ mask, float* __restrict__ O)
{
    extern __shared__ unsigned sa[];
    unsigned* Qs = sa + OFF_QS;   // [128][68] tf32, [q][d]
    unsigned* Ks = sa + OFF_KS;   // [64][68] tf32, [s][d]
    unsigned* Ps = sa + OFF_PS;   // [128][68] tf32, [q][s]
    unsigned* Vs = sa + OFF_VS;   // [64*64] tf32, swizzled [d][s]
    float* mAdd = (float*)(sa + OFF_MA);  // [512]

    const int tid = threadIdx.x;
    const int lane = tid & 31;
    const int warp = tid >> 5;
    const int n0 = blockIdx.x * 128;
    const int h = blockIdx.y;
    const int b = blockIdx.z;

    const float* Qb = Q + ((size_t)b * N_ + n0) * D_ + h * HD_;
    const float* Kb = KV + (size_t)b * S_ * (2 * D_) + h * HD_;
    const float* Vb = Kb + D_;
    const int* mb = mask + b * S_;
    float* Ob = O + ((size_t)b * N_ + n0) * D_ + h * HD_;

    // load Q tile (pre-scaled by 0.125), cvt to tf32.
    // 128 rows x 16 float4/row = 2048 float4 over 256 threads -> 8 iters.
#pragma unroll
    for (int l = 0; l < 8; l++) {
        int idx = tid + l * 256;
        int q = idx >> 4;
        int d4 = (idx & 15) * 4;
        float4 v = *(const float4*)(Qb + (size_t)q * D_ + d4);
        uint4 u = make_uint4(f2tf(v.x * 0.125f), f2tf(v.y * 0.125f),
                             f2tf(v.z * 0.125f), f2tf(v.w * 0.125f));
        *(uint4*)(Qs + q * APAD + d4) = u;
    }
    // mask addends
    for (int s = tid; s < S_; s += 256) mAdd[s] = mb[s] ? -1e5f : 0.f;

    float o[8][4];
#pragma unroll
    for (int i = 0; i < 8; i++)
#pragma unroll
        for (int r = 0; r < 4; r++) o[i][r] = 0.f;
    float mrow0 = -1e30f, mrow1 = -1e30f, lrow0 = 0.f, lrow1 = 0.f;

    const int q0 = warp * 16 + (lane >> 2);

    __syncthreads();

    for (int st = 0; st < S_; st += 64) {
        // load K tile [s][d] and V tile transposed+swizzled [d][s]: 64 x 16 float4
#pragma unroll
        for (int l = 0; l < 4; l++) {
            int idx = tid + l * 256;
            int s = idx >> 4;
            int d4 = (idx & 15) * 4;
            float4 vk = *(const float4*)(Kb + (size_t)(st + s) * (2 * D_) + d4);
            uint4 uk = make_uint4(f2tf(vk.x), f2tf(vk.y), f2tf(vk.z), f2tf(vk.w));
            *(uint4*)(Ks + s * APAD + d4) = uk;
            float4 vv = *(const float4*)(Vb + (size_t)(st + s) * (2 * D_) + d4);
            Vs[vswz(d4 + 0, s)] = f2tf(vv.x);
            Vs[vswz(d4 + 1, s)] = f2tf(vv.y);
            Vs[vswz(d4 + 2, s)] = f2tf(vv.z);
            Vs[vswz(d4 + 3, s)] = f2tf(vv.w);
        }
        __syncthreads();

        // QK^T: scores [16q x 64s] per warp
        float sc[8][4];
#pragma unroll
        for (int nt = 0; nt < 8; nt++)
#pragma unroll
            for (int r = 0; r < 4; r++) sc[nt][r] = 0.f;

#pragma unroll
        for (int ks = 0; ks < 64; ks += 8) {
            unsigned af[4];
            const unsigned* pq = Qs + q0 * APAD + ks + (lane & 3);
            af[0] = pq[0];
            af[1] = pq[8 * APAD];
            af[2] = pq[4];
            af[3] = pq[8 * APAD + 4];
#pragma unroll
            for (int nt = 0; nt < 8; nt++) {
                unsigned bf[2];
                const unsigned* pk = Ks + (nt * 8 + (lane >> 2)) * APAD + ks + (lane & 3);
                bf[0] = pk[0];
                bf[1] = pk[4];
                mma_tf32(sc[nt], af, bf);
            }
        }

        // mask + online softmax (rows q0, q0+8)
        float rm0 = -1e30f, rm1 = -1e30f;
#pragma unroll
        for (int nt = 0; nt < 8; nt++) {
            int col = st + nt * 8 + (lane & 3) * 2;
            float a0 = mAdd[col], a1 = mAdd[col + 1];
            sc[nt][0] += a0; sc[nt][1] += a1;
            sc[nt][2] += a0; sc[nt][3] += a1;
            rm0 = fmaxf(rm0, fmaxf(sc[nt][0], sc[nt][1]));
            rm1 = fmaxf(rm1, fmaxf(sc[nt][2], sc[nt][3]));
        }
        rm0 = fmaxf(rm0, __shfl_xor_sync(0xffffffffu, rm0, 1));
        rm0 = fmaxf(rm0, __shfl_xor_sync(0xffffffffu, rm0, 2));
        rm1 = fmaxf(rm1, __shfl_xor_sync(0xffffffffu, rm1, 1));
        rm1 = fmaxf(rm1, __shfl_xor_sync(0xffffffffu, rm1, 2));

        float mn0 = fmaxf(mrow0, rm0), mn1 = fmaxf(mrow1, rm1);
        float c0 = __expf(mrow0 - mn0), c1 = __expf(mrow1 - mn1);
        float rs0 = 0.f, rs1 = 0.f;
#pragma unroll
        for (int nt = 0; nt < 8; nt++) {
            sc[nt][0] = __expf(sc[nt][0] - mn0);
            sc[nt][1] = __expf(sc[nt][1] - mn0);
            sc[nt][2] = __expf(sc[nt][2] - mn1);
            sc[nt][3] = __expf(sc[nt][3] - mn1);
            rs0 += sc[nt][0] + sc[nt][1];
            rs1 += sc[nt][2] + sc[nt][3];
        }
        rs0 += __shfl_xor_sync(0xffffffffu, rs0, 1);
        rs0 += __shfl_xor_sync(0xffffffffu, rs0, 2);
        rs1 += __shfl_xor_sync(0xffffffffu, rs1, 1);
        rs1 += __shfl_xor_sync(0xffffffffu, rs1, 2);

        lrow0 = lrow0 * c0 + rs0;
        lrow1 = lrow1 * c1 + rs1;
        mrow0 = mn0;
        mrow1 = mn1;

        // rescale O accumulators
#pragma unroll
        for (int dt = 0; dt < 8; dt++) {
            o[dt][0] *= c0; o[dt][1] *= c0;
            o[dt][2] *= c1; o[dt][3] *= c1;
        }

        // write P to smem (tf32); PV below only reads this warp's own rows
#pragma unroll
        for (int nt = 0; nt < 8; nt++) {
            int col = nt * 8 + (lane & 3) * 2;
            *(uint2*)(Ps + q0 * APAD + col) = make_uint2(f2tf(sc[nt][0]), f2tf(sc[nt][1]));
            *(uint2*)(Ps + (q0 + 8) * APAD + col) = make_uint2(f2tf(sc[nt][2]), f2tf(sc[nt][3]));
        }
        __syncwarp();

        // O += P @ V
#pragma unroll
        for (int ss = 0; ss < 64; ss += 8) {
            unsigned af[4];
            const unsigned* pp = Ps + q0 * APAD + ss + (lane & 3);
            af[0] = pp[0];
            af[1] = pp[8 * APAD];
            af[2] = pp[4];
            af[3] = pp[8 * APAD + 4];
#pragma unroll
            for (int dt = 0; dt < 8; dt++) {
                int d = dt * 8 + (lane >> 2);
                unsigned bf[2];
                bf[0] = Vs[vswz(d, ss + (lane & 3))];
                bf[1] = Vs[vswz(d, ss + 4 + (lane & 3))];
                mma_tf32(o[dt], af, bf);
            }
        }
        __syncthreads();
    }

    // epilogue: normalize and store
    float inv0 = 1.0f / lrow0, inv1 = 1.0f / lrow1;
#pragma unroll
    for (int dt = 0; dt < 8; dt++) {
        int col = dt * 8 + (lane & 3) * 2;
        float2 v0, v1;
        v0.x = o[dt][0] * inv0; v0.y = o[dt][1] * inv0;
        v1.x = o[dt][2] * inv1; v1.y = o[dt][3] * inv1;
        *(float2*)(Ob + (size_t)q0 * D_ + col) = v0;
        *(float2*)(Ob + (size_t)(q0 + 8) * D_ + col) = v1;
    }
}

// ---------------------------------------------------------------------------
// Launch. Inputs: x, context, context_mask(int32), wq, bq, wkv, bkv, wp, bp
// ---------------------------------------------------------------------------
extern "C" void kernel_launch(void* const* d_in, const int* in_sizes, int n_in,
                              void* d_out, int out_size)
{
    const float* x = (const float*)d_in[0];
    const float* ctx = (const float*)d_in[1];
    const int* mask = (const int*)d_in[2];
    const float* wq = (const float*)d_in[3];
    const float* bq = (const float*)d_in[4];
    const float* wkv = (const float*)d_in[5];
    const float* bkv = (const float*)d_in[6];
    const float* wp = (const float*)d_in[7];
    const float* bp = (const float*)d_in[8];
    float* out = (float*)d_out;

    float *Qp, *KVp, *Op;
    cudaGetSymbolAddress((void**)&Qp, g_Q);
    cudaGetSymbolAddress((void**)&KVp, g_KV);
    cudaGetSymbolAddress((void**)&Op, g_O);

    int gemm_smem = 4 * GTILE * (int)sizeof(unsigned);   // 73728
    int attn_smem = ATTN_SMEM_U32 * (int)sizeof(unsigned);  // ~105KB

    cudaFuncSetAttribute((const void*)gemm_tf32,
                         cudaFuncAttributeMaxDynamicSharedMemorySize, gemm_smem);
    cudaFuncSetAttribute((const void*)attn_tf32,
                         cudaFuncAttributeMaxDynamicSharedMemorySize, attn_smem);

    // Q projection: [B*N, D] x [D, D]^T
    gemm_tf32<<<dim3(D_ / 128, (B_ * N_) / 128), 256, gemm_smem>>>(x, wq, bq, Qp, B_ * N_, D_, D_);
    // KV projection: [B*S, D] x [2D, D]^T
    gemm_tf32<<<dim3((2 * D_) / 128, (B_ * S_) / 128), 256, gemm_smem>>>(ctx, wkv, bkv, KVp, B_ * S_, 2 * D_, D_);
    // attention
    attn_tf32<<<dim3(N_ / 128, H_, B_), 256, attn_smem>>>(Qp, KVp, mask, Op);
    // output projection
    gemm_tf32<<<dim3(D_ / 128, (B_ * N_) / 128), 256, gemm_smem>>>(Op, wp, bp, out, B_ * N_, D_, D_);
}

// round 10
// speedup vs baseline: 1.1748x; 1.0046x over previous
#include <cuda_runtime.h>
#include <math.h>

// Problem constants
#define B_ 8
#define N_ 4096
#define S_ 512
#define D_ 512
#define H_ 8
#define HD_ 64

// Scratch (allocation-free rule: __device__ globals)
__device__ float g_Q[(size_t)B_ * N_ * D_];
__device__ float g_KV[(size_t)B_ * S_ * 2 * D_];
__device__ float g_O[(size_t)B_ * N_ * D_];

// ---------------------------------------------------------------------------
// tf32 helpers
// ---------------------------------------------------------------------------
__device__ __forceinline__ unsigned f2tf(float x) {
    unsigned r;
    asm("cvt.rna.tf32.f32 %0, %1;" : "=r"(r) : "f"(x));
    return r;
}

__device__ __forceinline__ void mma_tf32(float* d, const unsigned* a, const unsigned* b) {
    asm volatile(
        "mma.sync.aligned.m16n8k8.row.col.f32.tf32.tf32.f32 "
        "{%0,%1,%2,%3}, {%4,%5,%6,%7}, {%8,%9}, {%0,%1,%2,%3};\n"
        : "+f"(d[0]), "+f"(d[1]), "+f"(d[2]), "+f"(d[3])
        : "r"(a[0]), "r"(a[1]), "r"(a[2]), "r"(a[3]), "r"(b[0]), "r"(b[1]));
}

// ---------------------------------------------------------------------------
// GEMM: C[m][n] = sum_k A[m][k] * W[n][k] + bias[n]   (tf32 tensor cores)
// BM=BN=128, BK=32. 256 threads = 8 warps (2m x 4n), warp tile 64x32.
// KD compile-time so the k-loop (16 iters) unrolls with static buffer toggles.
// ---------------------------------------------------------------------------
#define GPAD 36
#define GTILE (128 * GPAD)

template <int KD>
__global__ __launch_bounds__(256, 2) void gemm_tf32(
    const float* __restrict__ A, const float* __restrict__ W,
    const float* __restrict__ bias, float* __restrict__ C,
    int M, int Nd)
{
    extern __shared__ unsigned sg[];
    unsigned* As = sg;                // [2][128][36]
    unsigned* Ws = sg + 2 * GTILE;    // [2][128][36]

    const int tid = threadIdx.x;
    const int lane = tid & 31;
    const int warp = tid >> 5;
    const int wm = warp >> 2;         // 0..1
    const int wn = warp & 3;          // 0..3
    const int m0 = blockIdx.y * 128;
    const int n0 = blockIdx.x * 128;

    float acc[4][4][4];
#pragma unroll
    for (int i = 0; i < 4; i++)
#pragma unroll
        for (int j = 0; j < 4; j++)
#pragma unroll
            for (int r = 0; r < 4; r++) acc[i][j][r] = 0.f;

    float4 pa[4], pw[4];
    constexpr int nkt = KD / 32;

    // prefetch tile 0
#pragma unroll
    for (int l = 0; l < 4; l++) {
        int idx = tid + l * 256;
        int row = idx >> 3;
        int c4 = (idx & 7) * 4;
        pa[l] = *(const float4*)(A + (size_t)(m0 + row) * KD + c4);
        pw[l] = *(const float4*)(W + (size_t)(n0 + row) * KD + c4);
    }
#pragma unroll
    for (int l = 0; l < 4; l++) {
        int idx = tid + l * 256;
        int row = idx >> 3;
        int c4 = (idx & 7) * 4;
        uint4 ua = make_uint4(f2tf(pa[l].x), f2tf(pa[l].y), f2tf(pa[l].z), f2tf(pa[l].w));
        uint4 uw = make_uint4(f2tf(pw[l].x), f2tf(pw[l].y), f2tf(pw[l].z), f2tf(pw[l].w));
        *(uint4*)(As + row * GPAD + c4) = ua;
        *(uint4*)(Ws + row * GPAD + c4) = uw;
    }
    __syncthreads();

#pragma unroll 2
    for (int kt = 0; kt < nkt; kt++) {
        if (kt + 1 < nkt) {
#pragma unroll
            for (int l = 0; l < 4; l++) {
                int idx = tid + l * 256;
                int row = idx >> 3;
                int c4 = (idx & 7) * 4;
                pa[l] = *(const float4*)(A + (size_t)(m0 + row) * KD + (kt + 1) * 32 + c4);
                pw[l] = *(const float4*)(W + (size_t)(n0 + row) * KD + (kt + 1) * 32 + c4);
            }
        }
        const unsigned* Ab = As + (kt & 1) * GTILE + (wm * 64) * GPAD;
        const unsigned* Wb = Ws + (kt & 1) * GTILE + (wn * 32) * GPAD;

#pragma unroll
        for (int ks = 0; ks < 32; ks += 8) {
            unsigned af[4][4], bf[4][2];
#pragma unroll
            for (int mt = 0; mt < 4; mt++) {
                const unsigned* p = Ab + (mt * 16 + (lane >> 2)) * GPAD + ks + (lane & 3);
                af[mt][0] = p[0];
                af[mt][1] = p[8 * GPAD];
                af[mt][2] = p[4];
                af[mt][3] = p[8 * GPAD + 4];
            }
#pragma unroll
            for (int nt = 0; nt < 4; nt++) {
                const unsigned* p = Wb + (nt * 8 + (lane >> 2)) * GPAD + ks + (lane & 3);
                bf[nt][0] = p[0];
                bf[nt][1] = p[4];
            }
#pragma unroll
            for (int mt = 0; mt < 4; mt++)
#pragma unroll
                for (int nt = 0; nt < 4; nt++)
                    mma_tf32(acc[mt][nt], af[mt], bf[nt]);
        }
        // Store next tile into the OTHER buffer (its readers finished before
        // the previous barrier), then one barrier.
        if (kt + 1 < nkt) {
            unsigned* Ad = As + ((kt + 1) & 1) * GTILE;
            unsigned* Wd = Ws + ((kt + 1) & 1) * GTILE;
#pragma unroll
            for (int l = 0; l < 4; l++) {
                int idx = tid + l * 256;
                int row = idx >> 3;
                int c4 = (idx & 7) * 4;
                uint4 ua = make_uint4(f2tf(pa[l].x), f2tf(pa[l].y), f2tf(pa[l].z), f2tf(pa[l].w));
                uint4 uw = make_uint4(f2tf(pw[l].x), f2tf(pw[l].y), f2tf(pw[l].z), f2tf(pw[l].w));
                *(uint4*)(Ad + row * GPAD + c4) = ua;
                *(uint4*)(Wd + row * GPAD + c4) = uw;
            }
            __syncthreads();
        }
    }

    // epilogue + bias
#pragma unroll
    for (int mt = 0; mt < 4; mt++) {
        int row0 = m0 + wm * 64 + mt * 16 + (lane >> 2);
#pragma unroll
        for (int nt = 0; nt < 4; nt++) {
            int col = n0 + wn * 32 + nt * 8 + (lane & 3) * 2;
            float2 bb = *(const float2*)(bias + col);
            float2 v0, v1;
            v0.x = acc[mt][nt][0] + bb.x;
            v0.y = acc[mt][nt][1] + bb.y;
            v1.x = acc[mt][nt][2] + bb.x;
            v1.y = acc[mt][nt][3] + bb.y;
            *(float2*)(C + (size_t)row0 * Nd + col) = v0;
            *(float2*)(C + (size_t)(row0 + 8) * Nd + col) = v1;
        }
    }
}

// ---------------------------------------------------------------------------
// Flash attention, tf32 tensor cores. CTA = 256 queries of one (b,h).
// 256 threads (8 warps); each warp owns 32 q-rows (two m16 tiles, mt=0..1).
// S-tiles of 64.
// ---------------------------------------------------------------------------
#define APAD 68
#define QT 256
// u32 offsets in dynamic smem
#define OFF_QS 0
#define OFF_KS (QT * APAD)
#define OFF_PS (QT * APAD + 64 * APAD)
#define OFF_VS (2 * QT * APAD + 64 * APAD)
#define OFF_MA (2 * QT * APAD + 64 * APAD + 64 * 64)
#define ATTN_SMEM_U32 (2 * QT * APAD + 64 * APAD + 64 * 64 + 512)

// V swizzle: element (d, s) stored at d*64 + ((s + 4d + (d>>3)) & 63)
__device__ __forceinline__ int vswz(int d, int s) {
    return d * 64 + ((s + 4 * d + (d >> 3)) & 63);
}

__global__ __launch_bounds__(256, 1) void attn_tf32(
    const float* __restrict__ Q, const float* __restrict__ KV,
    const int* __restrict__ mask, float* __restrict__ O)
{
    extern __shared__ unsigned sa[];
    unsigned* Qs = sa + OFF_QS;   // [256][68] tf32, [q][d]
    unsigned* Ks = sa + OFF_KS;   // [64][68] tf32, [s][d]
    unsigned* Ps = sa + OFF_PS;   // [256][68] tf32, [q][s]
    unsigned* Vs = sa + OFF_VS;   // [64*64] tf32, swizzled [d][s]
    float* mAdd = (float*)(sa + OFF_MA);  // [512]

    const int tid = threadIdx.x;
    const int lane = tid & 31;
    const int warp = tid >> 5;
    const int n0 = blockIdx.x * QT;
    const int h = blockIdx.y;
    const int b = blockIdx.z;

    const float* Qb = Q + ((size_t)b * N_ + n0) * D_ + h * HD_;
    const float* Kb = KV + (size_t)b * S_ * (2 * D_) + h * HD_;
    const float* Vb = Kb + D_;
    const int* mb = mask + b * S_;
    float* Ob = O + ((size_t)b * N_ + n0) * D_ + h * HD_;

    // load Q tile (pre-scaled by 0.125), cvt to tf32.
    // 256 rows x 16 float4/row = 4096 float4 over 256 threads -> 16 iters.
#pragma unroll
    for (int l = 0; l < 16; l++) {
        int idx = tid + l * 256;
        int q = idx >> 4;
        int d4 = (idx & 15) * 4;
        float4 v = *(const float4*)(Qb + (size_t)q * D_ + d4);
        uint4 u = make_uint4(f2tf(v.x * 0.125f), f2tf(v.y * 0.125f),
                             f2tf(v.z * 0.125f), f2tf(v.w * 0.125f));
        *(uint4*)(Qs + q * APAD + d4) = u;
    }
    // mask addends
    for (int s = tid; s < S_; s += 256) mAdd[s] = mb[s] ? -1e5f : 0.f;

    float o[2][8][4];
#pragma unroll
    for (int mt = 0; mt < 2; mt++)
#pragma unroll
        for (int i = 0; i < 8; i++)
#pragma unroll
            for (int r = 0; r < 4; r++) o[mt][i][r] = 0.f;
    float mrow[2][2], lrow[2][2];
#pragma unroll
    for (int mt = 0; mt < 2; mt++) {
        mrow[mt][0] = -1e30f; mrow[mt][1] = -1e30f;
        lrow[mt][0] = 0.f;    lrow[mt][1] = 0.f;
    }

    const int q0 = warp * 32 + (lane >> 2);   // mt block adds +16

    __syncthreads();

    for (int st = 0; st < S_; st += 64) {
        // load K tile [s][d] and V tile transposed+swizzled [d][s]: 64 x 16 float4
#pragma unroll
        for (int l = 0; l < 4; l++) {
            int idx = tid + l * 256;
            int s = idx >> 4;
            int d4 = (idx & 15) * 4;
            float4 vk = *(const float4*)(Kb + (size_t)(st + s) * (2 * D_) + d4);
            uint4 uk = make_uint4(f2tf(vk.x), f2tf(vk.y), f2tf(vk.z), f2tf(vk.w));
            *(uint4*)(Ks + s * APAD + d4) = uk;
            float4 vv = *(const float4*)(Vb + (size_t)(st + s) * (2 * D_) + d4);
            Vs[vswz(d4 + 0, s)] = f2tf(vv.x);
            Vs[vswz(d4 + 1, s)] = f2tf(vv.y);
            Vs[vswz(d4 + 2, s)] = f2tf(vv.z);
            Vs[vswz(d4 + 3, s)] = f2tf(vv.w);
        }
        __syncthreads();

        // QK^T: scores [32q x 64s] per warp (two m16 tiles)
        float sc[2][8][4];
#pragma unroll
        for (int mt = 0; mt < 2; mt++)
#pragma unroll
            for (int nt = 0; nt < 8; nt++)
#pragma unroll
                for (int r = 0; r < 4; r++) sc[mt][nt][r] = 0.f;

#pragma unroll
        for (int ks = 0; ks < 64; ks += 8) {
            unsigned af[2][4];
#pragma unroll
            for (int mt = 0; mt < 2; mt++) {
                const unsigned* pq = Qs + (q0 + mt * 16) * APAD + ks + (lane & 3);
                af[mt][0] = pq[0];
                af[mt][1] = pq[8 * APAD];
                af[mt][2] = pq[4];
                af[mt][3] = pq[8 * APAD + 4];
            }
#pragma unroll
            for (int nt = 0; nt < 8; nt++) {
                unsigned bf[2];
                const unsigned* pk = Ks + (nt * 8 + (lane >> 2)) * APAD + ks + (lane & 3);
                bf[0] = pk[0];
                bf[1] = pk[4];
                mma_tf32(sc[0][nt], af[0], bf);
                mma_tf32(sc[1][nt], af[1], bf);
            }
        }

        // mask + online softmax, per mt block (rows q0+mt*16, q0+mt*16+8)
#pragma unroll
        for (int mt = 0; mt < 2; mt++) {
            float rm0 = -1e30f, rm1 = -1e30f;
#pragma unroll
            for (int nt = 0; nt < 8; nt++) {
                int col = st + nt * 8 + (lane & 3) * 2;
                float a0 = mAdd[col], a1 = mAdd[col + 1];
                sc[mt][nt][0] += a0; sc[mt][nt][1] += a1;
                sc[mt][nt][2] += a0; sc[mt][nt][3] += a1;
                rm0 = fmaxf(rm0, fmaxf(sc[mt][nt][0], sc[mt][nt][1]));
                rm1 = fmaxf(rm1, fmaxf(sc[mt][nt][2], sc[mt][nt][3]));
            }
            rm0 = fmaxf(rm0, __shfl_xor_sync(0xffffffffu, rm0, 1));
            rm0 = fmaxf(rm0, __shfl_xor_sync(0xffffffffu, rm0, 2));
            rm1 = fmaxf(rm1, __shfl_xor_sync(0xffffffffu, rm1, 1));
            rm1 = fmaxf(rm1, __shfl_xor_sync(0xffffffffu, rm1, 2));

            float mn0 = fmaxf(mrow[mt][0], rm0), mn1 = fmaxf(mrow[mt][1], rm1);
            float c0 = __expf(mrow[mt][0] - mn0), c1 = __expf(mrow[mt][1] - mn1);
            float rs0 = 0.f, rs1 = 0.f;
#pragma unroll
            for (int nt = 0; nt < 8; nt++) {
                sc[mt][nt][0] = __expf(sc[mt][nt][0] - mn0);
                sc[mt][nt][1] = __expf(sc[mt][nt][1] - mn0);
                sc[mt][nt][2] = __expf(sc[mt][nt][2] - mn1);
                sc[mt][nt][3] = __expf(sc[mt][nt][3] - mn1);
                rs0 += sc[mt][nt][0] + sc[mt][nt][1];
                rs1 += sc[mt][nt][2] + sc[mt][nt][3];
            }
            rs0 += __shfl_xor_sync(0xffffffffu, rs0, 1);
            rs0 += __shfl_xor_sync(0xffffffffu, rs0, 2);
            rs1 += __shfl_xor_sync(0xffffffffu, rs1, 1);
            rs1 += __shfl_xor_sync(0xffffffffu, rs1, 2);

            lrow[mt][0] = lrow[mt][0] * c0 + rs0;
            lrow[mt][1] = lrow[mt][1] * c1 + rs1;
            mrow[mt][0] = mn0;
            mrow[mt][1] = mn1;

            // rescale O accumulators
#pragma unroll
            for (int dt = 0; dt < 8; dt++) {
                o[mt][dt][0] *= c0; o[mt][dt][1] *= c0;
                o[mt][dt][2] *= c1; o[mt][dt][3] *= c1;
            }

            // write P to smem (tf32); PV below reads only this warp's rows
#pragma unroll
            for (int nt = 0; nt < 8; nt++) {
                int col = nt * 8 + (lane & 3) * 2;
                *(uint2*)(Ps + (q0 + mt * 16) * APAD + col) =
                    make_uint2(f2tf(sc[mt][nt][0]), f2tf(sc[mt][nt][1]));
                *(uint2*)(Ps + (q0 + mt * 16 + 8) * APAD + col) =
                    make_uint2(f2tf(sc[mt][nt][2]), f2tf(sc[mt][nt][3]));
            }
        }
        __syncwarp();

        // O += P @ V
#pragma unroll
        for (int ss = 0; ss < 64; ss += 8) {
            unsigned af[2][4];
#pragma unroll
            for (int mt = 0; mt < 2; mt++) {
                const unsigned* pp = Ps + (q0 + mt * 16) * APAD + ss + (lane & 3);
                af[mt][0] = pp[0];
                af[mt][1] = pp[8 * APAD];
                af[mt][2] = pp[4];
                af[mt][3] = pp[8 * APAD + 4];
            }
#pragma unroll
            for (int dt = 0; dt < 8; dt++) {
                int d = dt * 8 + (lane >> 2);
                unsigned bf[2];
                bf[0] = Vs[vswz(d, ss + (lane & 3))];
                bf[1] = Vs[vswz(d, ss + 4 + (lane & 3))];
                mma_tf32(o[0][dt], af[0], bf);
                mma_tf32(o[1][dt], af[1], bf);
            }
        }
        __syncthreads();
    }

    // epilogue: normalize and store
#pragma unroll
    for (int mt = 0; mt < 2; mt++) {
        float inv0 = 1.0f / lrow[mt][0], inv1 = 1.0f / lrow[mt][1];
#pragma unroll
        for (int dt = 0; dt < 8; dt++) {
            int col = dt * 8 + (lane & 3) * 2;
            float2 v0, v1;
            v0.x = o[mt][dt][0] * inv0; v0.y = o[mt][dt][1] * inv0;
            v1.x = o[mt][dt][2] * inv1; v1.y = o[mt][dt][3] * inv1;
            *(float2*)(Ob + (size_t)(q0 + mt * 16) * D_ + col) = v0;
            *(float2*)(Ob + (size_t)(q0 + mt * 16 + 8) * D_ + col) = v1;
        }
    }
}

// ---------------------------------------------------------------------------
// Launch. Inputs: x, context, context_mask(int32), wq, bq, wkv, bkv, wp, bp
// ---------------------------------------------------------------------------
extern "C" void kernel_launch(void* const* d_in, const int* in_sizes, int n_in,
                              void* d_out, int out_size)
{
    const float* x = (const float*)d_in[0];
    const float* ctx = (const float*)d_in[1];
    const int* mask = (const int*)d_in[2];
    const float* wq = (const float*)d_in[3];
    const float* bq = (const float*)d_in[4];
    const float* wkv = (const float*)d_in[5];
    const float* bkv = (const float*)d_in[6];
    const float* wp = (const float*)d_in[7];
    const float* bp = (const float*)d_in[8];
    float* out = (float*)d_out;

    float *Qp, *KVp, *Op;
    cudaGetSymbolAddress((void**)&Qp, g_Q);
    cudaGetSymbolAddress((void**)&KVp, g_KV);
    cudaGetSymbolAddress((void**)&Op, g_O);

    int gemm_smem = 4 * GTILE * (int)sizeof(unsigned);      // 73728
    int attn_smem = ATTN_SMEM_U32 * (int)sizeof(unsigned);  // ~175KB

    cudaFuncSetAttribute((const void*)gemm_tf32<512>,
                         cudaFuncAttributeMaxDynamicSharedMemorySize, gemm_smem);
    cudaFuncSetAttribute((const void*)attn_tf32,
                         cudaFuncAttributeMaxDynamicSharedMemorySize, attn_smem);

    // Q projection: [B*N, D] x [D, D]^T
    gemm_tf32<512><<<dim3(D_ / 128, (B_ * N_) / 128), 256, gemm_smem>>>(x, wq, bq, Qp, B_ * N_, D_);
    // KV projection: [B*S, D] x [2D, D]^T
    gemm_tf32<512><<<dim3((2 * D_) / 128, (B_ * S_) / 128), 256, gemm_smem>>>(ctx, wkv, bkv, KVp, B_ * S_, 2 * D_);
    // attention
    attn_tf32<<<dim3(N_ / QT, H_, B_), 256, attn_smem>>>(Qp, KVp, mask, Op);
    // output projection
    gemm_tf32<512><<<dim3(D_ / 128, (B_ * N_) / 128), 256, gemm_smem>>>(Op, wp, bp, out, B_ * N_, D_);
}